// round 1
// baseline (speedup 1.0000x reference)
#include <cuda_runtime.h>
#include <math.h>

#define BATCH 4
#define TLEN  2048
#define CDIM  2048
#define HS    64
#define NH    32
#define MTOT  (BATCH*TLEN)   /* 8192 */

/* ---------------- scratch (static device allocations; no cudaMalloc) ------- */
__device__ float g_X  [(size_t)MTOT*CDIM];
__device__ float g_XX1[(size_t)MTOT*128];
__device__ float g_MIX[4][(size_t)MTOT*CDIM];
__device__ float g_XW1[(size_t)MTOT*32];
__device__ float g_MW [(size_t)MTOT*CDIM];
__device__ float g_XW [(size_t)MTOT*CDIM];
__device__ float g_T1 [(size_t)MTOT*128];
__device__ float g_DEC[(size_t)MTOT*CDIM];
__device__ float g_R  [(size_t)MTOT*CDIM];
__device__ float g_K  [(size_t)MTOT*CDIM];
__device__ float g_V  [(size_t)MTOT*CDIM];
__device__ float g_V2 [(size_t)MTOT*CDIM];
__device__ float g_Y  [(size_t)MTOT*CDIM];
__device__ float g_YN [(size_t)MTOT*CDIM];

/* ---------------- big NT SGEMM: C[m,n] = sum_k A[m,k]*B[n,k] ----------------
   BM=BN=128, BK=16, 256 threads, 8x8 microtile, register prefetch of the
   next global chunk so LDG latency hides under the 1024-FMA inner loop.   */
__global__ __launch_bounds__(256, 2)
void gemm_nt128(const float* __restrict__ A, const float* __restrict__ B,
                float* __restrict__ C, int M, int N, int K)
{
    __shared__ float As[16][132];
    __shared__ float Bs[16][132];
    const int tid = threadIdx.x;
    const int bm = blockIdx.y * 128;
    const int bn = blockIdx.x * 128;
    const int tx = tid & 15;
    const int ty = tid >> 4;

    float acc[8][8];
#pragma unroll
    for (int r = 0; r < 8; r++)
#pragma unroll
        for (int c = 0; c < 8; c++) acc[r][c] = 0.f;

    const int r0 = tid >> 2, kq0 = (tid & 3) << 2;
    const int i1 = tid + 256;
    const int r1 = i1 >> 2,  kq1 = (i1 & 3) << 2;

    float4 fa0 = *(const float4*)&A[(size_t)(bm + r0) * K + kq0];
    float4 fa1 = *(const float4*)&A[(size_t)(bm + r1) * K + kq1];
    float4 fb0 = *(const float4*)&B[(size_t)(bn + r0) * K + kq0];
    float4 fb1 = *(const float4*)&B[(size_t)(bn + r1) * K + kq1];

    for (int k0 = 0; k0 < K; k0 += 16) {
        As[kq0+0][r0] = fa0.x; As[kq0+1][r0] = fa0.y; As[kq0+2][r0] = fa0.z; As[kq0+3][r0] = fa0.w;
        As[kq1+0][r1] = fa1.x; As[kq1+1][r1] = fa1.y; As[kq1+2][r1] = fa1.z; As[kq1+3][r1] = fa1.w;
        Bs[kq0+0][r0] = fb0.x; Bs[kq0+1][r0] = fb0.y; Bs[kq0+2][r0] = fb0.z; Bs[kq0+3][r0] = fb0.w;
        Bs[kq1+0][r1] = fb1.x; Bs[kq1+1][r1] = fb1.y; Bs[kq1+2][r1] = fb1.z; Bs[kq1+3][r1] = fb1.w;
        __syncthreads();
        if (k0 + 16 < K) {
            const int kb = k0 + 16;
            fa0 = *(const float4*)&A[(size_t)(bm + r0) * K + kb + kq0];
            fa1 = *(const float4*)&A[(size_t)(bm + r1) * K + kb + kq1];
            fb0 = *(const float4*)&B[(size_t)(bn + r0) * K + kb + kq0];
            fb1 = *(const float4*)&B[(size_t)(bn + r1) * K + kb + kq1];
        }
#pragma unroll
        for (int kk = 0; kk < 16; kk++) {
            float a[8], b[8];
            *(float4*)&a[0] = *(const float4*)&As[kk][ty*8];
            *(float4*)&a[4] = *(const float4*)&As[kk][ty*8+4];
            *(float4*)&b[0] = *(const float4*)&Bs[kk][tx*8];
            *(float4*)&b[4] = *(const float4*)&Bs[kk][tx*8+4];
#pragma unroll
            for (int r = 0; r < 8; r++)
#pragma unroll
                for (int c = 0; c < 8; c++)
                    acc[r][c] = fmaf(a[r], b[c], acc[r][c]);
        }
        __syncthreads();
    }
#pragma unroll
    for (int r = 0; r < 8; r++) {
        float* cp = &C[(size_t)(bm + ty*8 + r) * N + bn + tx*8];
        *(float4*)cp     = make_float4(acc[r][0],acc[r][1],acc[r][2],acc[r][3]);
        *(float4*)(cp+4) = make_float4(acc[r][4],acc[r][5],acc[r][6],acc[r][7]);
    }
}

/* ---------------- generic NN GEMM: C[m,n] = f(sum_k A[m,lda..]*B[k,n]) ------
   BM=64, BN=128, BK=32. epi: 0=none, 1=tanh, 2=exp(-exp(bias[n]+acc)).    */
__global__ __launch_bounds__(256, 2)
void gemm_nn(const float* __restrict__ A, int lda, int aoff,
             const float* __restrict__ B, int ldb,
             float* __restrict__ C, int ldc,
             int M, int N, int K, int epi, const float* __restrict__ bias)
{
    __shared__ float As[64][36];
    __shared__ float Bs[32][128];
    const int tid = threadIdx.x;
    const int bm = blockIdx.y * 64;
    const int bn = blockIdx.x * 128;
    const int cx = tid & 31;
    const int rg = tid >> 5;

    float4 acc[8];
#pragma unroll
    for (int r = 0; r < 8; r++) acc[r] = make_float4(0.f,0.f,0.f,0.f);

    for (int k0 = 0; k0 < K; k0 += 32) {
#pragma unroll
        for (int u = 0; u < 2; u++) {
            int i = tid + 256*u;
            int r = i >> 3, kq = (i & 7) << 2;
            float4 v = *(const float4*)&A[(size_t)(bm + r) * lda + aoff + k0 + kq];
            *(float4*)&As[r][kq] = v;
        }
#pragma unroll
        for (int u = 0; u < 4; u++) {
            int i = tid + 256*u;
            int kr = i >> 5, nq = (i & 31) << 2;
            float4 v = make_float4(0.f,0.f,0.f,0.f);
            if (bn + nq < N)
                v = *(const float4*)&B[(size_t)(k0 + kr) * ldb + bn + nq];
            *(float4*)&Bs[kr][nq] = v;
        }
        __syncthreads();
#pragma unroll 8
        for (int k = 0; k < 32; k++) {
            float4 bv = *(const float4*)&Bs[k][cx << 2];
#pragma unroll
            for (int r = 0; r < 8; r++) {
                float a = As[rg*8 + r][k];
                acc[r].x = fmaf(a, bv.x, acc[r].x);
                acc[r].y = fmaf(a, bv.y, acc[r].y);
                acc[r].z = fmaf(a, bv.z, acc[r].z);
                acc[r].w = fmaf(a, bv.w, acc[r].w);
            }
        }
        __syncthreads();
    }
    const int n = bn + (cx << 2);
    if (n < N) {
#pragma unroll
        for (int r = 0; r < 8; r++) {
            float4 o = acc[r];
            if (epi == 1) {
                o.x = tanhf(o.x); o.y = tanhf(o.y); o.z = tanhf(o.z); o.w = tanhf(o.w);
            } else if (epi == 2) {
                o.x = expf(-expf(bias[n+0] + o.x));
                o.y = expf(-expf(bias[n+1] + o.y));
                o.z = expf(-expf(bias[n+2] + o.z));
                o.w = expf(-expf(bias[n+3] + o.w));
            }
            *(float4*)&C[(size_t)(bm + rg*8 + r) * ldc + n] = o;
        }
    }
}

/* ---------------- elementwise: XW = x + dxprev*(time_maa_w + mw) ----------- */
__global__ void ew_xw_kernel(const float* __restrict__ X, const float* __restrict__ shiftst,
                             const float* __restrict__ MW, const float* __restrict__ tmw,
                             float* __restrict__ XW)
{
    int i4 = blockIdx.x * 256 + threadIdx.x;          /* over MTOT*CDIM/4 */
    int m = i4 >> 9, c4 = i4 & 511;
    int t = m & (TLEN-1), b = m >> 11;
    const float4* X4 = (const float4*)X;
    float4 x  = X4[i4];
    float4 xp = (t == 0) ? ((const float4*)shiftst)[(b << 9) + c4] : X4[i4 - 512];
    float4 mw = ((const float4*)MW)[i4];
    float4 w  = ((const float4*)tmw)[c4];
    float4 o;
    o.x = x.x + (xp.x - x.x) * (w.x + mw.x);
    o.y = x.y + (xp.y - x.y) * (w.y + mw.y);
    o.z = x.z + (xp.z - x.z) * (w.z + mw.z);
    o.w = x.w + (xp.w - x.w) * (w.w + mw.w);
    ((float4*)XW)[i4] = o;
}

/* ---------------- elementwise: r, k, v, v2 --------------------------------- */
__global__ void ew_rkvv_kernel(const float* __restrict__ X, const float* __restrict__ shiftst,
    const float* __restrict__ M0, const float* __restrict__ M1,
    const float* __restrict__ M2, const float* __restrict__ M3,
    const float* __restrict__ DEC,
    const float* __restrict__ tmr, const float* __restrict__ tmk,
    const float* __restrict__ tmv, const float* __restrict__ tmv2,
    const float* __restrict__ trec, const float* __restrict__ tkey,
    float* __restrict__ R, float* __restrict__ K,
    float* __restrict__ V, float* __restrict__ V2)
{
    int i4 = blockIdx.x * 256 + threadIdx.x;
    int m = i4 >> 9, c4 = i4 & 511;
    int t = m & (TLEN-1), b = m >> 11;
    const float4* X4 = (const float4*)X;
    float4 x  = X4[i4];
    float4 xp = (t == 0) ? ((const float4*)shiftst)[(b << 9) + c4] : X4[i4 - 512];
    float4 m0 = ((const float4*)M0)[i4];
    float4 m1 = ((const float4*)M1)[i4];
    float4 m2 = ((const float4*)M2)[i4];
    float4 m3 = ((const float4*)M3)[i4];
    float4 d  = ((const float4*)DEC)[i4];
    float4 cr = ((const float4*)tmr)[c4];
    float4 ck = ((const float4*)tmk)[c4];
    float4 cv = ((const float4*)tmv)[c4];
    float4 c2 = ((const float4*)tmv2)[c4];
    float4 rc = ((const float4*)trec)[c4];
    float4 kc = ((const float4*)tkey)[c4];
    float4 o_r, o_k, o_v, o_w;
#define RKVV_APPLY(f) do { \
    float dxv = xp.f - x.f; \
    o_r.f = (x.f + dxv*(cr.f + m0.f)) * rc.f; \
    o_k.f = (x.f + dxv*(ck.f + m1.f)) * kc.f * (1.f - d.f); \
    o_v.f =  x.f + dxv*(cv.f + m2.f); \
    o_w.f =  x.f + dxv*(c2.f + m3.f); \
} while(0)
    RKVV_APPLY(x); RKVV_APPLY(y); RKVV_APPLY(z); RKVV_APPLY(w);
#undef RKVV_APPLY
    ((float4*)R )[i4] = o_r;
    ((float4*)K )[i4] = o_k;
    ((float4*)V )[i4] = o_v;
    ((float4*)V2)[i4] = o_w;
}

/* ---------------- WKV sequential scan --------------------------------------
   1 block per (b,h). tid = j*4 + iq: thread owns S[iq*16 .. iq*16+15][j] in
   registers. Per step: load r/k/d/v vectors to double-buffered shared (each
   group of 64 threads streams one of the 4 vectors with a depth-4 register
   prefetch pipeline to hide DRAM latency), y = shuffle-reduced r·S column,
   S = d*S + k*v_j. u == 0 in this model, so y uses the pre-update state.   */
__global__ __launch_bounds__(256, 1)
void wkv_kernel(const float* __restrict__ Rp, const float* __restrict__ Kp,
                const float* __restrict__ Vp, const float* __restrict__ Dp,
                const float* __restrict__ S0, float* __restrict__ Y)
{
    const int bh = blockIdx.x;
    const int b = bh >> 5, h = bh & (NH-1);
    const int tid = threadIdx.x;
    const int j = tid >> 2, iq = tid & 3, i0 = iq << 4;

    float S[16];
    const float* s0p = S0 + (size_t)bh * HS * HS;
#pragma unroll
    for (int ii = 0; ii < 16; ii++) S[ii] = s0p[(i0 + ii) * HS + j];

    __shared__ float sbuf[2][4][64];     /* [buf][r,k,d,v][i or j] */

    const int grp = tid >> 6, lane = tid & 63;
    const size_t base = ((size_t)b * TLEN) * CDIM + h * HS;
    const float* myp =
        ((grp == 0) ? Rp : (grp == 1) ? Kp : (grp == 2) ? Dp : Vp) + base + lane;

    float pre[4];
#pragma unroll
    for (int u = 0; u < 4; u++) pre[u] = myp[(size_t)u * CDIM];

    const size_t ybase = base;
    for (int tc = 0; tc < TLEN; tc += 4) {
        float cur[4];
#pragma unroll
        for (int u = 0; u < 4; u++) cur[u] = pre[u];
        if (tc + 4 < TLEN) {
#pragma unroll
            for (int u = 0; u < 4; u++) pre[u] = myp[(size_t)(tc + 4 + u) * CDIM];
        }
#pragma unroll
        for (int u = 0; u < 4; u++) {
            const int t = tc + u;
            const int buf = t & 1;
            sbuf[buf][grp][lane] = cur[u];
            __syncthreads();
            const float4* r4 = (const float4*)sbuf[buf][0];
            const float4* k4 = (const float4*)sbuf[buf][1];
            const float4* d4 = (const float4*)sbuf[buf][2];
            const float vj = sbuf[buf][3][j];
            float y = 0.f;
#pragma unroll
            for (int q = 0; q < 4; q++) {
                float4 rv = r4[iq*4 + q];
                y = fmaf(rv.x, S[q*4+0], y);
                y = fmaf(rv.y, S[q*4+1], y);
                y = fmaf(rv.z, S[q*4+2], y);
                y = fmaf(rv.w, S[q*4+3], y);
            }
#pragma unroll
            for (int q = 0; q < 4; q++) {
                float4 dv = d4[iq*4 + q];
                float4 kv = k4[iq*4 + q];
                S[q*4+0] = fmaf(dv.x, S[q*4+0], kv.x * vj);
                S[q*4+1] = fmaf(dv.y, S[q*4+1], kv.y * vj);
                S[q*4+2] = fmaf(dv.z, S[q*4+2], kv.z * vj);
                S[q*4+3] = fmaf(dv.w, S[q*4+3], kv.w * vj);
            }
            y += __shfl_xor_sync(0xffffffffu, y, 1);
            y += __shfl_xor_sync(0xffffffffu, y, 2);
            if (iq == 0) Y[ybase + (size_t)t * CDIM + j] = y;
        }
    }
}

/* ---------------- fused add + LayerNorm ------------------------------------ */
__global__ void ln_kernel(const float* __restrict__ Y, const float* __restrict__ V2,
                          const float* __restrict__ gamma, const float* __restrict__ beta,
                          float* __restrict__ YN)
{
    const int m = blockIdx.x;
    const int tid = threadIdx.x;
    const float4* y4 = (const float4*)(Y  + (size_t)m * CDIM);
    const float4* v4 = (const float4*)(V2 + (size_t)m * CDIM);
    float4 vals[2];
    float s = 0.f, s2 = 0.f;
#pragma unroll
    for (int u = 0; u < 2; u++) {
        float4 a = y4[tid + u*256], b = v4[tid + u*256];
        float4 v = make_float4(a.x+b.x, a.y+b.y, a.z+b.z, a.w+b.w);
        vals[u] = v;
        s  += v.x + v.y + v.z + v.w;
        s2 += v.x*v.x + v.y*v.y + v.z*v.z + v.w*v.w;
    }
#pragma unroll
    for (int o = 16; o; o >>= 1) {
        s  += __shfl_xor_sync(0xffffffffu, s,  o);
        s2 += __shfl_xor_sync(0xffffffffu, s2, o);
    }
    __shared__ float sh[2][8];
    const int w = tid >> 5, l = tid & 31;
    if (l == 0) { sh[0][w] = s; sh[1][w] = s2; }
    __syncthreads();
    s = 0.f; s2 = 0.f;
#pragma unroll
    for (int i = 0; i < 8; i++) { s += sh[0][i]; s2 += sh[1][i]; }
    const float mu   = s  * (1.f / CDIM);
    const float var  = s2 * (1.f / CDIM) - mu * mu;
    const float rstd = rsqrtf(var + 1e-5f);
    const float4* g4 = (const float4*)gamma;
    const float4* b4 = (const float4*)beta;
    float4* o4 = (float4*)(YN + (size_t)m * CDIM);
#pragma unroll
    for (int u = 0; u < 2; u++) {
        int c4 = tid + u*256;
        float4 g = g4[c4], bb = b4[c4], v = vals[u];
        float4 o;
        o.x = (v.x - mu) * rstd * g.x + bb.x;
        o.y = (v.y - mu) * rstd * g.y + bb.y;
        o.z = (v.z - mu) * rstd * g.z + bb.z;
        o.w = (v.w - mu) * rstd * g.w + bb.w;
        o4[c4] = o;
    }
}

/* ---------------- launch --------------------------------------------------- */
extern "C" void kernel_launch(void* const* d_in, const int* in_sizes, int n_in,
                              void* d_out, int out_size)
{
    const float* x_in     = (const float*)d_in[0];
    const float* shiftst  = (const float*)d_in[1];
    const float* wkvstate = (const float*)d_in[2];
    const float* tmr      = (const float*)d_in[3];
    const float* tmk      = (const float*)d_in[4];
    const float* tmv      = (const float*)d_in[5];
    const float* tmv2     = (const float*)d_in[6];
    const float* maa_w1   = (const float*)d_in[7];
    const float* maa_w2   = (const float*)d_in[8];
    const float* tmw      = (const float*)d_in[9];
    const float* ww1      = (const float*)d_in[10];
    const float* ww2      = (const float*)d_in[11];
    const float* tdecay   = (const float*)d_in[12];
    const float* dw1      = (const float*)d_in[13];
    const float* dw2      = (const float*)d_in[14];
    /* d_in[15] = time_faaaa: unused (u == 0 in this model) */
    const float* trec     = (const float*)d_in[16];
    const float* tkey     = (const float*)d_in[17];
    const float* value_w  = (const float*)d_in[18];
    const float* output_w = (const float*)d_in[19];
    const float* gamma    = (const float*)d_in[20];
    const float* beta     = (const float*)d_in[21];
    float* out = (float*)d_out;

    float *pX, *pXX1, *pMIX, *pXW1, *pMW, *pXW, *pT1, *pDEC, *pR, *pK, *pV, *pV2, *pY, *pYN;
    cudaGetSymbolAddress((void**)&pX,   g_X);
    cudaGetSymbolAddress((void**)&pXX1, g_XX1);
    cudaGetSymbolAddress((void**)&pMIX, g_MIX);
    cudaGetSymbolAddress((void**)&pXW1, g_XW1);
    cudaGetSymbolAddress((void**)&pMW,  g_MW);
    cudaGetSymbolAddress((void**)&pXW,  g_XW);
    cudaGetSymbolAddress((void**)&pT1,  g_T1);
    cudaGetSymbolAddress((void**)&pDEC, g_DEC);
    cudaGetSymbolAddress((void**)&pR,   g_R);
    cudaGetSymbolAddress((void**)&pK,   g_K);
    cudaGetSymbolAddress((void**)&pV,   g_V);
    cudaGetSymbolAddress((void**)&pV2,  g_V2);
    cudaGetSymbolAddress((void**)&pY,   g_Y);
    cudaGetSymbolAddress((void**)&pYN,  g_YN);

    const size_t SZ = (size_t)MTOT * CDIM;
    const int EW_BLOCKS = (int)(SZ / 4 / 256);

    /* X = x_in @ value_w^T */
    gemm_nt128<<<dim3(CDIM/128, MTOT/128), 256>>>(x_in, value_w, pX, MTOT, CDIM, CDIM);
    /* XX1 = tanh(x_in @ maa_w1) */
    gemm_nn<<<dim3(1, MTOT/64), 256>>>(x_in, CDIM, 0, maa_w1, 128, pXX1, 128,
                                       MTOT, 128, CDIM, 1, (const float*)0);
    /* MIX[f] = XX1[:, f*32:(f+1)*32] @ maa_w2[f] */
    for (int f = 0; f < 4; f++)
        gemm_nn<<<dim3(CDIM/128, MTOT/64), 256>>>(pXX1, 128, f*32,
                                                  maa_w2 + (size_t)f*32*CDIM, CDIM,
                                                  pMIX + (size_t)f*SZ, CDIM,
                                                  MTOT, CDIM, 32, 0, (const float*)0);
    /* XW1 = tanh(X @ w_w1) */
    gemm_nn<<<dim3(1, MTOT/64), 256>>>(pX, CDIM, 0, ww1, 32, pXW1, 32,
                                       MTOT, 32, CDIM, 1, (const float*)0);
    /* MW = XW1 @ w_w2 */
    gemm_nn<<<dim3(CDIM/128, MTOT/64), 256>>>(pXW1, 32, 0, ww2, CDIM, pMW, CDIM,
                                              MTOT, CDIM, 32, 0, (const float*)0);
    /* XW = X + dxprev*(time_maa_w + MW) */
    ew_xw_kernel<<<EW_BLOCKS, 256>>>(pX, shiftst, pMW, tmw, pXW);
    /* T1 = tanh(XW @ decay_w1) */
    gemm_nn<<<dim3(1, MTOT/64), 256>>>(pXW, CDIM, 0, dw1, 128, pT1, 128,
                                       MTOT, 128, CDIM, 1, (const float*)0);
    /* DEC = exp(-exp(time_decay + T1 @ decay_w2)) */
    gemm_nn<<<dim3(CDIM/128, MTOT/64), 256>>>(pT1, 128, 0, dw2, CDIM, pDEC, CDIM,
                                              MTOT, CDIM, 128, 2, tdecay);
    /* r, k, v, v2 */
    ew_rkvv_kernel<<<EW_BLOCKS, 256>>>(pX, shiftst,
                                       pMIX, pMIX + SZ, pMIX + 2*SZ, pMIX + 3*SZ,
                                       pDEC, tmr, tmk, tmv, tmv2, trec, tkey,
                                       pR, pK, pV, pV2);
    /* WKV scan */
    wkv_kernel<<<BATCH*NH, 256>>>(pR, pK, pV, pDEC, wkvstate, pY);
    /* yn = LN(y + v2) */
    ln_kernel<<<MTOT, 256>>>(pY, pV2, gamma, beta, pYN);
    /* out = yn @ output_w^T */
    gemm_nt128<<<dim3(CDIM/128, MTOT/128), 256>>>(pYN, output_w, out, MTOT, CDIM, CDIM);
}